// round 1
// baseline (speedup 1.0000x reference)
#include <cuda_runtime.h>

// Problem constants (fixed shapes)
constexpr int NB   = 16;          // batch
constexpr int SEQ  = 512;         // sequence length
constexpr int DM   = 512;         // model dim
constexpr int NH   = 8;           // heads
constexpr int DK   = 64;          // head dim
constexpr int MR   = NB * SEQ;    // 8192 rows
constexpr float SCALE = 0.125f;   // DK^-0.5
constexpr float NEGC  = -9000000000000000.0f;
constexpr float LN_EPS = 1e-5f;

// Scratch (device globals — no allocation allowed)
__device__ float g_h  [MR * DM];
__device__ float g_q  [MR * DM];
__device__ float g_k  [MR * DM];
__device__ float g_v  [MR * DM];
__device__ float g_sc [(size_t)NB * NH * SEQ * SEQ]; // 128 MiB
__device__ float g_ctx[MR * DM];
__device__ float g_h2 [MR * DM];

// ---------------------------------------------------------------------------
// Reductions (256-thread blocks)
// ---------------------------------------------------------------------------
__device__ __forceinline__ float warpReduceSum(float v) {
#pragma unroll
    for (int o = 16; o; o >>= 1) v += __shfl_xor_sync(0xffffffffu, v, o);
    return v;
}
__device__ __forceinline__ float warpReduceMax(float v) {
#pragma unroll
    for (int o = 16; o; o >>= 1) v = fmaxf(v, __shfl_xor_sync(0xffffffffu, v, o));
    return v;
}
__device__ __forceinline__ float blockReduceSum(float v) {
    __shared__ float sh[8];
    v = warpReduceSum(v);
    if ((threadIdx.x & 31) == 0) sh[threadIdx.x >> 5] = v;
    __syncthreads();
    float r = (threadIdx.x < 8) ? sh[threadIdx.x] : 0.f;
    if (threadIdx.x < 32) r = warpReduceSum(r);
    if (threadIdx.x == 0) sh[0] = r;
    __syncthreads();
    float out = sh[0];
    __syncthreads();
    return out;
}
__device__ __forceinline__ float blockReduceMax(float v) {
    __shared__ float sh[8];
    v = warpReduceMax(v);
    if ((threadIdx.x & 31) == 0) sh[threadIdx.x >> 5] = v;
    __syncthreads();
    float r = (threadIdx.x < 8) ? sh[threadIdx.x] : -3.4e38f;
    if (threadIdx.x < 32) r = warpReduceMax(r);
    if (threadIdx.x == 0) sh[0] = r;
    __syncthreads();
    float out = sh[0];
    __syncthreads();
    return out;
}

// ---------------------------------------------------------------------------
// SGEMM: C[MR x DM] = A[MR x DM] @ W[DM x DM] + bias (optional relu)
// 64x64 tile, BK=16, 256 threads, 4x4 per-thread microtile.
// grid = (DM/64, MR/64)
// ---------------------------------------------------------------------------
__global__ void __launch_bounds__(256) sgemm_bias(
    const float* __restrict__ A, const float* __restrict__ W,
    const float* __restrict__ bias, float* __restrict__ C, int relu)
{
    __shared__ float As[16][68];
    __shared__ float Bs[16][64];
    const int tid = threadIdx.x;
    const int tx = tid & 15, ty = tid >> 4;
    const int rowBase = blockIdx.y * 64;
    const int colBase = blockIdx.x * 64;

    const int ar = tid >> 2;        // 0..63
    const int ac = (tid & 3) * 4;   // 0,4,8,12
    const int br = tid >> 4;        // 0..15
    const int bc = (tid & 15) * 4;  // 0..60

    float acc[4][4] = {};

    for (int k0 = 0; k0 < DM; k0 += 16) {
        float4 av = *(const float4*)&A[(size_t)(rowBase + ar) * DM + k0 + ac];
        As[ac + 0][ar] = av.x; As[ac + 1][ar] = av.y;
        As[ac + 2][ar] = av.z; As[ac + 3][ar] = av.w;
        *(float4*)&Bs[br][bc] = *(const float4*)&W[(size_t)(k0 + br) * DM + colBase + bc];
        __syncthreads();
#pragma unroll
        for (int k = 0; k < 16; k++) {
            float a[4], b[4];
#pragma unroll
            for (int i = 0; i < 4; i++) a[i] = As[k][ty * 4 + i];
#pragma unroll
            for (int j = 0; j < 4; j++) b[j] = Bs[k][tx * 4 + j];
#pragma unroll
            for (int i = 0; i < 4; i++)
#pragma unroll
                for (int j = 0; j < 4; j++) acc[i][j] += a[i] * b[j];
        }
        __syncthreads();
    }
#pragma unroll
    for (int i = 0; i < 4; i++) {
        int r = rowBase + ty * 4 + i;
#pragma unroll
        for (int j = 0; j < 4; j++) {
            int c = colBase + tx * 4 + j;
            float v = acc[i][j] + bias[c];
            if (relu) v = fmaxf(v, 0.f);
            C[(size_t)r * DM + c] = v;
        }
    }
}

// ---------------------------------------------------------------------------
// LayerNorm over last dim (512), in-place safe. grid = MR, 256 threads.
// ---------------------------------------------------------------------------
__global__ void __launch_bounds__(256) ln_kernel(
    float* __restrict__ h, const float* __restrict__ g, const float* __restrict__ b)
{
    const int row = blockIdx.x;
    float* p = h + (size_t)row * DM;
    const int t = threadIdx.x;
    float v0 = p[t], v1 = p[t + 256];
    float mu = blockReduceSum(v0 + v1) * (1.f / DM);
    float d0 = v0 - mu, d1 = v1 - mu;
    float var = blockReduceSum(d0 * d0 + d1 * d1) * (1.f / DM);
    float rs = rsqrtf(var + LN_EPS);
    p[t]       = d0 * rs * g[t]       + b[t];
    p[t + 256] = d1 * rs * g[t + 256] + b[t + 256];
}

// ---------------------------------------------------------------------------
// Scores: S[b,h,q,k] = SCALE * sum_d Q[b,q,h,d]*K[b,k,h,d], then mask.
// grid = (SEQ/64, SEQ/64, NB*NH), 256 threads. K-dim = 64.
// ---------------------------------------------------------------------------
__global__ void __launch_bounds__(256) scores_kernel(
    const float* __restrict__ Q, const float* __restrict__ Km,
    const float* __restrict__ adj, const int* __restrict__ use_adj,
    float* __restrict__ S)
{
    const int bh = blockIdx.z;
    const int b  = bh >> 3;
    const int h  = bh & 7;
    const float* Ab = Q  + (size_t)b * SEQ * DM + h * DK;
    const float* Bb = Km + (size_t)b * SEQ * DM + h * DK;

    __shared__ float As[16][68];
    __shared__ float Bs[16][68];
    const int tid = threadIdx.x;
    const int tx = tid & 15, ty = tid >> 4;
    const int qBase = blockIdx.y * 64;
    const int kBase = blockIdx.x * 64;
    const int ar = tid >> 2;
    const int ac = (tid & 3) * 4;

    float acc[4][4] = {};

    for (int k0 = 0; k0 < DK; k0 += 16) {
        float4 av = *(const float4*)&Ab[(size_t)(qBase + ar) * DM + k0 + ac];
        As[ac + 0][ar] = av.x; As[ac + 1][ar] = av.y;
        As[ac + 2][ar] = av.z; As[ac + 3][ar] = av.w;
        float4 bv = *(const float4*)&Bb[(size_t)(kBase + ar) * DM + k0 + ac];
        Bs[ac + 0][ar] = bv.x; Bs[ac + 1][ar] = bv.y;
        Bs[ac + 2][ar] = bv.z; Bs[ac + 3][ar] = bv.w;
        __syncthreads();
#pragma unroll
        for (int k = 0; k < 16; k++) {
            float a[4], bv2[4];
#pragma unroll
            for (int i = 0; i < 4; i++) a[i] = As[k][ty * 4 + i];
#pragma unroll
            for (int j = 0; j < 4; j++) bv2[j] = Bs[k][tx * 4 + j];
#pragma unroll
            for (int i = 0; i < 4; i++)
#pragma unroll
                for (int j = 0; j < 4; j++) acc[i][j] += a[i] * bv2[j];
        }
        __syncthreads();
    }

    const int ua = *use_adj;
    float* Sb = S + (size_t)bh * SEQ * SEQ;
    const float* adjb = adj + (size_t)b * SEQ * SEQ;
#pragma unroll
    for (int i = 0; i < 4; i++) {
        int qi = qBase + ty * 4 + i;
#pragma unroll
        for (int j = 0; j < 4; j++) {
            int ki = kBase + tx * 4 + j;
            float s = acc[i][j] * SCALE;
            if (ua) {
                float a = adjb[(size_t)qi * SEQ + ki];
                // EXACT reference semantics: where(a>0, s, NEG) * a
                s = (a > 0.f ? s : NEGC) * a;
            }
            Sb[(size_t)qi * SEQ + ki] = s;
        }
    }
}

// ---------------------------------------------------------------------------
// Row softmax over 512 entries. grid = NB*NH*SEQ, 256 threads.
// ---------------------------------------------------------------------------
__global__ void __launch_bounds__(256) softmax_kernel(float* __restrict__ S)
{
    float* p = S + (size_t)blockIdx.x * SEQ;
    const int t = threadIdx.x;
    float v0 = p[t], v1 = p[t + 256];
    float mx = blockReduceMax(fmaxf(v0, v1));
    float e0 = __expf(v0 - mx), e1 = __expf(v1 - mx);
    float inv = 1.f / blockReduceSum(e0 + e1);
    p[t]       = e0 * inv;
    p[t + 256] = e1 * inv;
}

// ---------------------------------------------------------------------------
// ctx[b,q,h,d] = sum_k attn[b,h,q,k] * V[b,k,h,d]
// grid = (SEQ/64, NB*NH), 256 threads. Per block: 64 q-rows x 64 d-cols, K=512.
// ---------------------------------------------------------------------------
__global__ void __launch_bounds__(256) ctx_kernel(
    const float* __restrict__ S, const float* __restrict__ V, float* __restrict__ Cx)
{
    const int bh = blockIdx.y;
    const int b  = bh >> 3;
    const int h  = bh & 7;
    const float* A  = S  + (size_t)bh * SEQ * SEQ;
    const float* Bb = V  + (size_t)b * SEQ * DM + h * DK;
    float*       Cb = Cx + (size_t)b * SEQ * DM + h * DK;

    __shared__ float As[16][68];
    __shared__ float Bs[16][64];
    const int tid = threadIdx.x;
    const int tx = tid & 15, ty = tid >> 4;
    const int rowBase = blockIdx.x * 64;
    const int ar = tid >> 2;
    const int ac = (tid & 3) * 4;
    const int br = tid >> 4;
    const int bc = (tid & 15) * 4;

    float acc[4][4] = {};

    for (int k0 = 0; k0 < SEQ; k0 += 16) {
        float4 av = *(const float4*)&A[(size_t)(rowBase + ar) * SEQ + k0 + ac];
        As[ac + 0][ar] = av.x; As[ac + 1][ar] = av.y;
        As[ac + 2][ar] = av.z; As[ac + 3][ar] = av.w;
        *(float4*)&Bs[br][bc] = *(const float4*)&Bb[(size_t)(k0 + br) * DM + bc];
        __syncthreads();
#pragma unroll
        for (int k = 0; k < 16; k++) {
            float a[4], bv[4];
#pragma unroll
            for (int i = 0; i < 4; i++) a[i] = As[k][ty * 4 + i];
#pragma unroll
            for (int j = 0; j < 4; j++) bv[j] = Bs[k][tx * 4 + j];
#pragma unroll
            for (int i = 0; i < 4; i++)
#pragma unroll
                for (int j = 0; j < 4; j++) acc[i][j] += a[i] * bv[j];
        }
        __syncthreads();
    }
#pragma unroll
    for (int i = 0; i < 4; i++) {
        int r = rowBase + ty * 4 + i;
#pragma unroll
        for (int j = 0; j < 4; j++) {
            Cb[(size_t)r * DM + tx * 4 + j] = acc[i][j];
        }
    }
}

// ---------------------------------------------------------------------------
// Gate: coeff = sigmoid([x, h2] @ gw + gb); out = coeff*x + (1-coeff)*h2
// grid = MR, 256 threads.
// ---------------------------------------------------------------------------
__global__ void __launch_bounds__(256) gate_kernel(
    const float* __restrict__ x, const float* __restrict__ h2,
    const float* __restrict__ gw, const float* __restrict__ gb,
    float* __restrict__ out)
{
    const int row = blockIdx.x;
    const float* xr = x  + (size_t)row * DM;
    const float* hr = h2 + (size_t)row * DM;
    const int t = threadIdx.x;
    float s = xr[t] * gw[t] + xr[t + 256] * gw[t + 256]
            + hr[t] * gw[DM + t] + hr[t + 256] * gw[DM + t + 256];
    s = blockReduceSum(s) + gb[0];
    float c = 1.f / (1.f + __expf(-s));
    float* o = out + (size_t)row * DM;
    o[t]       = c * xr[t]       + (1.f - c) * hr[t];
    o[t + 256] = c * xr[t + 256] + (1.f - c) * hr[t + 256];
}

// ---------------------------------------------------------------------------
// Launch
// ---------------------------------------------------------------------------
extern "C" void kernel_launch(void* const* d_in, const int* in_sizes, int n_in,
                              void* d_out, int out_size)
{
    const float* x    = (const float*)d_in[0];
    const float* adj  = (const float*)d_in[1];
    const float* W_w  = (const float*)d_in[2];
    const float* W_b  = (const float*)d_in[3];
    const float* ln_g = (const float*)d_in[4];
    const float* ln_b = (const float*)d_in[5];
    const float* Wq   = (const float*)d_in[6];
    const float* bq   = (const float*)d_in[7];
    const float* Wk   = (const float*)d_in[8];
    const float* bk   = (const float*)d_in[9];
    const float* Wv   = (const float*)d_in[10];
    const float* bv   = (const float*)d_in[11];
    const float* Wo   = (const float*)d_in[12];
    const float* bo   = (const float*)d_in[13];
    const float* gw   = (const float*)d_in[14];
    const float* gb   = (const float*)d_in[15];
    const int* use_adj = (const int*)d_in[16];
    float* out = (float*)d_out;

    float *h, *q, *k, *v, *sc, *ctx, *h2;
    cudaGetSymbolAddress((void**)&h,   g_h);
    cudaGetSymbolAddress((void**)&q,   g_q);
    cudaGetSymbolAddress((void**)&k,   g_k);
    cudaGetSymbolAddress((void**)&v,   g_v);
    cudaGetSymbolAddress((void**)&sc,  g_sc);
    cudaGetSymbolAddress((void**)&ctx, g_ctx);
    cudaGetSymbolAddress((void**)&h2,  g_h2);

    dim3 gGemm(DM / 64, MR / 64);   // (8, 128)

    // h = LN(x @ W_w + W_b)
    sgemm_bias<<<gGemm, 256>>>(x, W_w, W_b, h, 0);
    ln_kernel<<<MR, 256>>>(h, ln_g, ln_b);

    // q, k, v projections
    sgemm_bias<<<gGemm, 256>>>(h, Wq, bq, q, 0);
    sgemm_bias<<<gGemm, 256>>>(h, Wk, bk, k, 0);
    sgemm_bias<<<gGemm, 256>>>(h, Wv, bv, v, 0);

    // attention scores + mask
    dim3 gSc(SEQ / 64, SEQ / 64, NB * NH);  // (8, 8, 128)
    scores_kernel<<<gSc, 256>>>(q, k, adj, use_adj, sc);

    // softmax
    softmax_kernel<<<NB * NH * SEQ, 256>>>(sc);

    // ctx = attn @ V
    dim3 gCtx(SEQ / 64, NB * NH);           // (8, 128)
    ctx_kernel<<<gCtx, 256>>>(sc, v, ctx);

    // h2 = relu(ctx @ Wo + bo)
    sgemm_bias<<<gGemm, 256>>>(ctx, Wo, bo, h2, 1);

    // gated residual
    gate_kernel<<<MR, 256>>>(x, h2, gw, gb, out);
}

// round 4
// speedup vs baseline: 1.4640x; 1.4640x over previous
#include <cuda_runtime.h>
#include <cuda_bf16.h>
#include <cstdint>

// Problem constants (fixed shapes)
constexpr int NB   = 16;          // batch
constexpr int SEQ  = 512;         // sequence length
constexpr int DM   = 512;         // model dim
constexpr int NH   = 8;           // heads
constexpr int DK   = 64;          // head dim
constexpr int MR   = NB * SEQ;    // 8192 rows
constexpr float SCALE = 0.125f;   // DK^-0.5
constexpr float NEGC  = -9000000000000000.0f;
constexpr float LN_EPS = 1e-5f;

// Scratch (device globals — no allocation allowed)
__device__ float g_h  [MR * DM];
__device__ float g_q  [MR * DM];
__device__ float g_k  [MR * DM];
__device__ float g_v  [MR * DM];
__device__ float g_sc [(size_t)NB * NH * SEQ * SEQ]; // 128 MiB
__device__ float g_ctx[MR * DM];
__device__ float g_h2 [MR * DM];
// bf16 hi/lo split of the 5 transposed weights, layout [N, K]
__device__ __nv_bfloat16 g_whi[5 * DM * DM];
__device__ __nv_bfloat16 g_wlo[5 * DM * DM];

// ---------------------------------------------------------------------------
// Helpers
// ---------------------------------------------------------------------------
__device__ __forceinline__ uint32_t smem_u32(const void* p) {
    uint32_t a;
    asm("{ .reg .u64 t; cvta.to.shared.u64 t, %1; cvt.u32.u64 %0, t; }" : "=r"(a) : "l"(p));
    return a;
}
__device__ __forceinline__ uint32_t swz(uint32_t off) { return off ^ ((off >> 3) & 0x70); }

__device__ __forceinline__ void split_bf16(float a, __nv_bfloat16& hi, __nv_bfloat16& lo) {
    hi = __float2bfloat16(a);
    lo = __float2bfloat16(a - __bfloat162float(hi));
}
__device__ __forceinline__ uint32_t pack2(__nv_bfloat16 a, __nv_bfloat16 b) {
    return (uint32_t)__bfloat16_as_ushort(a) | ((uint32_t)__bfloat16_as_ushort(b) << 16);
}

__device__ __forceinline__ void ldsm_x4(uint32_t* r, uint32_t addr) {
    asm volatile("ldmatrix.sync.aligned.m8n8.x4.shared.b16 {%0,%1,%2,%3}, [%4];"
                 : "=r"(r[0]), "=r"(r[1]), "=r"(r[2]), "=r"(r[3]) : "r"(addr));
}
__device__ __forceinline__ void mma_bf16(float* d, const uint32_t* a, const uint32_t* b) {
    asm volatile(
        "mma.sync.aligned.m16n8k16.row.col.f32.bf16.bf16.f32 "
        "{%0,%1,%2,%3}, {%4,%5,%6,%7}, {%8,%9}, {%0,%1,%2,%3};"
        : "+f"(d[0]), "+f"(d[1]), "+f"(d[2]), "+f"(d[3])
        : "r"(a[0]), "r"(a[1]), "r"(a[2]), "r"(a[3]), "r"(b[0]), "r"(b[1]));
}

// ---------------------------------------------------------------------------
// Weight prep: transpose W[K=512, N=512] -> Whi/Wlo [N, K] bf16 split.
// grid = (16, 16, 5), block = (32, 8)
// ---------------------------------------------------------------------------
__global__ void __launch_bounds__(256) prep_w(
    const float* __restrict__ W0, const float* __restrict__ W1,
    const float* __restrict__ W2, const float* __restrict__ W3,
    const float* __restrict__ W4)
{
    const float* W;
    switch (blockIdx.z) {
        case 0: W = W0; break;
        case 1: W = W1; break;
        case 2: W = W2; break;
        case 3: W = W3; break;
        default: W = W4; break;
    }
    __nv_bfloat16* oh = g_whi + (size_t)blockIdx.z * DM * DM;
    __nv_bfloat16* ol = g_wlo + (size_t)blockIdx.z * DM * DM;

    __shared__ float s[32][33];
    const int bx = blockIdx.x * 32, by = blockIdx.y * 32;
    const int tx = threadIdx.x, ty = threadIdx.y;
#pragma unroll
    for (int i = 0; i < 4; i++)
        s[ty + i * 8][tx] = W[(size_t)(by + ty + i * 8) * DM + bx + tx];
    __syncthreads();
#pragma unroll
    for (int i = 0; i < 4; i++) {
        int n = bx + ty + i * 8;
        int k = by + tx;
        float v = s[tx][ty + i * 8];
        __nv_bfloat16 hi, lo;
        split_bf16(v, hi, lo);
        oh[(size_t)n * DM + k] = hi;
        ol[(size_t)n * DM + k] = lo;
    }
}

// ---------------------------------------------------------------------------
// mma.sync GEMM: C[MR x 512] = A[MR x 512] @ W + bias (optional relu)
// W as bf16 hi/lo split in [N, K] layout (= mma "col" B operand).
// 2-term bf16 split: 3 mma products per tile for ~fp32-grade accuracy.
// CTA: 128x128 tile, BK=64 staged, 8 warps (2M x 4N), warp tile 64x32.
// grid = (4, 64), 256 threads, 64KB dynamic smem.
// ---------------------------------------------------------------------------
constexpr int GM_AHI = 0;
constexpr int GM_ALO = 16384;
constexpr int GM_BHI = 32768;
constexpr int GM_BLO = 49152;
constexpr int GM_TOTAL = 65536;

__global__ void __launch_bounds__(256) gemm_mma(
    const float* __restrict__ A,
    const __nv_bfloat16* __restrict__ Bhi, const __nv_bfloat16* __restrict__ Blo,
    const float* __restrict__ bias, float* __restrict__ C, int relu)
{
    extern __shared__ __align__(1024) char smem[];
    const uint32_t sb = smem_u32(smem);
    const int tid = threadIdx.x;
    const int lid = tid & 31;
    const int wid = tid >> 5;
    const int warpM = (wid >> 2) * 64;   // 0 or 64
    const int warpN = (wid & 3) * 32;    // 0,32,64,96
    const int rowBase = blockIdx.y * 128;
    const int colBase = blockIdx.x * 128;

    float acc[4][4][4];
#pragma unroll
    for (int i = 0; i < 4; i++)
#pragma unroll
        for (int j = 0; j < 4; j++)
#pragma unroll
            for (int r = 0; r < 4; r++) acc[i][j][r] = 0.f;

    // ldmatrix lane-address components
    const int a_row = (lid & 7) + ((lid >> 3) & 1) * 8;  // row within 16-row tile
    const int a_kh  = ((lid >> 4) & 1) * 8;              // k half
    const int b_nrow = (lid & 7) + ((lid >> 4) & 1) * 8; // n row (2 tiles per x4)
    const int b_kh   = ((lid >> 3) & 1) * 8;             // k half

    for (int s = 0; s < 8; s++) {
        const int k0 = s * 64;
        // ---- A tile 128x64 fp32 -> hi/lo bf16 planes ----
#pragma unroll
        for (int it = 0; it < 8; it++) {
            int i = tid + it * 256;            // 0..2047
            int row = i >> 4;
            int kk  = (i & 15) * 4;
            float4 v = *(const float4*)&A[(size_t)(rowBase + row) * DM + k0 + kk];
            __nv_bfloat16 h0, h1, h2, h3, l0, l1, l2, l3;
            split_bf16(v.x, h0, l0); split_bf16(v.y, h1, l1);
            split_bf16(v.z, h2, l2); split_bf16(v.w, h3, l3);
            uint32_t off = swz((uint32_t)(row * 128 + kk * 2));
            *(uint2*)(smem + GM_AHI + off) = make_uint2(pack2(h0, h1), pack2(h2, h3));
            *(uint2*)(smem + GM_ALO + off) = make_uint2(pack2(l0, l1), pack2(l2, l3));
        }
        // ---- B tile 128x64 bf16 (pre-split) ----
#pragma unroll
        for (int it = 0; it < 4; it++) {
            int i = tid + it * 256;            // 0..1023
            int row = i >> 3;
            int kk  = (i & 7) * 8;
            size_t gidx = (size_t)(colBase + row) * DM + k0 + kk;
            uint32_t off = swz((uint32_t)(row * 128 + kk * 2));
            *(uint4*)(smem + GM_BHI + off) = *(const uint4*)&Bhi[gidx];
            *(uint4*)(smem + GM_BLO + off) = *(const uint4*)&Blo[gidx];
        }
        __syncthreads();

#pragma unroll
        for (int ks = 0; ks < 4; ks++) {
            uint32_t ahi[4][4], alo[4][4], bhi[8], blo[8];
#pragma unroll
            for (int mi = 0; mi < 4; mi++) {
                uint32_t off = swz((uint32_t)((warpM + mi * 16 + a_row) * 128 + (ks * 16 + a_kh) * 2));
                ldsm_x4(ahi[mi], sb + GM_AHI + off);
                ldsm_x4(alo[mi], sb + GM_ALO + off);
            }
#pragma unroll
            for (int np = 0; np < 2; np++) {
                uint32_t off = swz((uint32_t)((warpN + np * 16 + b_nrow) * 128 + (ks * 16 + b_kh) * 2));
                ldsm_x4(bhi + np * 4, sb + GM_BHI + off);
                ldsm_x4(blo + np * 4, sb + GM_BLO + off);
            }
#pragma unroll
            for (int mi = 0; mi < 4; mi++)
#pragma unroll
                for (int ni = 0; ni < 4; ni++) {
                    mma_bf16(acc[mi][ni], ahi[mi], bhi + ni * 2);
                    mma_bf16(acc[mi][ni], ahi[mi], blo + ni * 2);
                    mma_bf16(acc[mi][ni], alo[mi], bhi + ni * 2);
                }
        }
        __syncthreads();
    }

    // ---- epilogue: registers -> gmem (float2 per mma tile row) ----
#pragma unroll
    for (int mi = 0; mi < 4; mi++) {
        int r0 = rowBase + warpM + mi * 16 + (lid >> 2);
#pragma unroll
        for (int ni = 0; ni < 4; ni++) {
            int c = colBase + warpN + ni * 8 + 2 * (lid & 3);
            float2 bb = *(const float2*)&bias[c];
            float v0 = acc[mi][ni][0] + bb.x;
            float v1 = acc[mi][ni][1] + bb.y;
            float v2 = acc[mi][ni][2] + bb.x;
            float v3 = acc[mi][ni][3] + bb.y;
            if (relu) {
                v0 = fmaxf(v0, 0.f); v1 = fmaxf(v1, 0.f);
                v2 = fmaxf(v2, 0.f); v3 = fmaxf(v3, 0.f);
            }
            *(float2*)&C[(size_t)r0 * DM + c]       = make_float2(v0, v1);
            *(float2*)&C[(size_t)(r0 + 8) * DM + c] = make_float2(v2, v3);
        }
    }
}

// ---------------------------------------------------------------------------
// Reductions (256-thread blocks)
// ---------------------------------------------------------------------------
__device__ __forceinline__ float warpReduceSum(float v) {
#pragma unroll
    for (int o = 16; o; o >>= 1) v += __shfl_xor_sync(0xffffffffu, v, o);
    return v;
}
__device__ __forceinline__ float warpReduceMax(float v) {
#pragma unroll
    for (int o = 16; o; o >>= 1) v = fmaxf(v, __shfl_xor_sync(0xffffffffu, v, o));
    return v;
}
__device__ __forceinline__ float blockReduceSum(float v) {
    __shared__ float sh[8];
    v = warpReduceSum(v);
    if ((threadIdx.x & 31) == 0) sh[threadIdx.x >> 5] = v;
    __syncthreads();
    float r = (threadIdx.x < 8) ? sh[threadIdx.x] : 0.f;
    if (threadIdx.x < 32) r = warpReduceSum(r);
    if (threadIdx.x == 0) sh[0] = r;
    __syncthreads();
    float out = sh[0];
    __syncthreads();
    return out;
}
__device__ __forceinline__ float blockReduceMax(float v) {
    __shared__ float sh[8];
    v = warpReduceMax(v);
    if ((threadIdx.x & 31) == 0) sh[threadIdx.x >> 5] = v;
    __syncthreads();
    float r = (threadIdx.x < 8) ? sh[threadIdx.x] : -3.4e38f;
    if (threadIdx.x < 32) r = warpReduceMax(r);
    if (threadIdx.x == 0) sh[0] = r;
    __syncthreads();
    float out = sh[0];
    __syncthreads();
    return out;
}

// ---------------------------------------------------------------------------
// LayerNorm over last dim (512), in-place. grid = MR, 256 threads.
// ---------------------------------------------------------------------------
__global__ void __launch_bounds__(256) ln_kernel(
    float* __restrict__ h, const float* __restrict__ g, const float* __restrict__ b)
{
    const int row = blockIdx.x;
    float* p = h + (size_t)row * DM;
    const int t = threadIdx.x;
    float v0 = p[t], v1 = p[t + 256];
    float mu = blockReduceSum(v0 + v1) * (1.f / DM);
    float d0 = v0 - mu, d1 = v1 - mu;
    float var = blockReduceSum(d0 * d0 + d1 * d1) * (1.f / DM);
    float rs = rsqrtf(var + LN_EPS);
    p[t]       = d0 * rs * g[t]       + b[t];
    p[t + 256] = d1 * rs * g[t + 256] + b[t + 256];
}

// ---------------------------------------------------------------------------
// Scores: S[b,h,q,k] = SCALE * sum_d Q[b,q,h,d]*K[b,k,h,d], then mask.
// grid = (SEQ/64, SEQ/64, NB*NH), 256 threads.
// ---------------------------------------------------------------------------
__global__ void __launch_bounds__(256) scores_kernel(
    const float* __restrict__ Q, const float* __restrict__ Km,
    const float* __restrict__ adj, const int* __restrict__ use_adj,
    float* __restrict__ S)
{
    const int bh = blockIdx.z;
    const int b  = bh >> 3;
    const int h  = bh & 7;
    const float* Ab = Q  + (size_t)b * SEQ * DM + h * DK;
    const float* Bb = Km + (size_t)b * SEQ * DM + h * DK;

    __shared__ float As[16][68];
    __shared__ float Bs[16][68];
    const int tid = threadIdx.x;
    const int tx = tid & 15, ty = tid >> 4;
    const int qBase = blockIdx.y * 64;
    const int kBase = blockIdx.x * 64;
    const int ar = tid >> 2;
    const int ac = (tid & 3) * 4;

    float acc[4][4] = {};

    for (int k0 = 0; k0 < DK; k0 += 16) {
        float4 av = *(const float4*)&Ab[(size_t)(qBase + ar) * DM + k0 + ac];
        As[ac + 0][ar] = av.x; As[ac + 1][ar] = av.y;
        As[ac + 2][ar] = av.z; As[ac + 3][ar] = av.w;
        float4 bv = *(const float4*)&Bb[(size_t)(kBase + ar) * DM + k0 + ac];
        Bs[ac + 0][ar] = bv.x; Bs[ac + 1][ar] = bv.y;
        Bs[ac + 2][ar] = bv.z; Bs[ac + 3][ar] = bv.w;
        __syncthreads();
#pragma unroll
        for (int k = 0; k < 16; k++) {
            float a[4], bv2[4];
#pragma unroll
            for (int i = 0; i < 4; i++) a[i] = As[k][ty * 4 + i];
#pragma unroll
            for (int j = 0; j < 4; j++) bv2[j] = Bs[k][tx * 4 + j];
#pragma unroll
            for (int i = 0; i < 4; i++)
#pragma unroll
                for (int j = 0; j < 4; j++) acc[i][j] += a[i] * bv2[j];
        }
        __syncthreads();
    }

    const int ua = *use_adj;
    float* Sb = S + (size_t)bh * SEQ * SEQ;
    const float* adjb = adj + (size_t)b * SEQ * SEQ;
#pragma unroll
    for (int i = 0; i < 4; i++) {
        int qi = qBase + ty * 4 + i;
#pragma unroll
        for (int j = 0; j < 4; j++) {
            int ki = kBase + tx * 4 + j;
            float s = acc[i][j] * SCALE;
            if (ua) {
                float a = adjb[(size_t)qi * SEQ + ki];
                // EXACT reference semantics: where(a>0, s, NEG) * a
                s = (a > 0.f ? s : NEGC) * a;
            }
            Sb[(size_t)qi * SEQ + ki] = s;
        }
    }
}

// ---------------------------------------------------------------------------
// Row softmax over 512 entries. grid = NB*NH*SEQ, 256 threads.
// ---------------------------------------------------------------------------
__global__ void __launch_bounds__(256) softmax_kernel(float* __restrict__ S)
{
    float* p = S + (size_t)blockIdx.x * SEQ;
    const int t = threadIdx.x;
    float v0 = p[t], v1 = p[t + 256];
    float mx = blockReduceMax(fmaxf(v0, v1));
    float e0 = __expf(v0 - mx), e1 = __expf(v1 - mx);
    float inv = 1.f / blockReduceSum(e0 + e1);
    p[t]       = e0 * inv;
    p[t + 256] = e1 * inv;
}

// ---------------------------------------------------------------------------
// ctx[b,q,h,d] = sum_k attn[b,h,q,k] * V[b,k,h,d]
// grid = (SEQ/64, NB*NH), 256 threads.
// ---------------------------------------------------------------------------
__global__ void __launch_bounds__(256) ctx_kernel(
    const float* __restrict__ S, const float* __restrict__ V, float* __restrict__ Cx)
{
    const int bh = blockIdx.y;
    const int b  = bh >> 3;
    const int h  = bh & 7;
    const float* A  = S  + (size_t)bh * SEQ * SEQ;
    const float* Bb = V  + (size_t)b * SEQ * DM + h * DK;
    float*       Cb = Cx + (size_t)b * SEQ * DM + h * DK;

    __shared__ float As[16][68];
    __shared__ float Bs[16][64];
    const int tid = threadIdx.x;
    const int tx = tid & 15, ty = tid >> 4;
    const int rowBase = blockIdx.x * 64;
    const int ar = tid >> 2;
    const int ac = (tid & 3) * 4;
    const int br = tid >> 4;
    const int bc = (tid & 15) * 4;

    float acc[4][4] = {};

    for (int k0 = 0; k0 < SEQ; k0 += 16) {
        float4 av = *(const float4*)&A[(size_t)(rowBase + ar) * SEQ + k0 + ac];
        As[ac + 0][ar] = av.x; As[ac + 1][ar] = av.y;
        As[ac + 2][ar] = av.z; As[ac + 3][ar] = av.w;
        *(float4*)&Bs[br][bc] = *(const float4*)&Bb[(size_t)(k0 + br) * DM + bc];
        __syncthreads();
#pragma unroll
        for (int k = 0; k < 16; k++) {
            float a[4], bv[4];
#pragma unroll
            for (int i = 0; i < 4; i++) a[i] = As[k][ty * 4 + i];
#pragma unroll
            for (int j = 0; j < 4; j++) bv[j] = Bs[k][tx * 4 + j];
#pragma unroll
            for (int i = 0; i < 4; i++)
#pragma unroll
                for (int j = 0; j < 4; j++) acc[i][j] += a[i] * bv[j];
        }
        __syncthreads();
    }
#pragma unroll
    for (int i = 0; i < 4; i++) {
        int r = rowBase + ty * 4 + i;
#pragma unroll
        for (int j = 0; j < 4; j++) {
            Cb[(size_t)r * DM + tx * 4 + j] = acc[i][j];
        }
    }
}

// ---------------------------------------------------------------------------
// Gate: coeff = sigmoid([x, h2] @ gw + gb); out = coeff*x + (1-coeff)*h2
// grid = MR, 256 threads.
// ---------------------------------------------------------------------------
__global__ void __launch_bounds__(256) gate_kernel(
    const float* __restrict__ x, const float* __restrict__ h2,
    const float* __restrict__ gw, const float* __restrict__ gb,
    float* __restrict__ out)
{
    const int row = blockIdx.x;
    const float* xr = x  + (size_t)row * DM;
    const float* hr = h2 + (size_t)row * DM;
    const int t = threadIdx.x;
    float s = xr[t] * gw[t] + xr[t + 256] * gw[t + 256]
            + hr[t] * gw[DM + t] + hr[t + 256] * gw[DM + t + 256];
    s = blockReduceSum(s) + gb[0];
    float c = 1.f / (1.f + __expf(-s));
    float* o = out + (size_t)row * DM;
    o[t]       = c * xr[t]       + (1.f - c) * hr[t];
    o[t + 256] = c * xr[t + 256] + (1.f - c) * hr[t + 256];
}

// ---------------------------------------------------------------------------
// Launch
// ---------------------------------------------------------------------------
extern "C" void kernel_launch(void* const* d_in, const int* in_sizes, int n_in,
                              void* d_out, int out_size)
{
    const float* x    = (const float*)d_in[0];
    const float* adj  = (const float*)d_in[1];
    const float* W_w  = (const float*)d_in[2];
    const float* W_b  = (const float*)d_in[3];
    const float* ln_g = (const float*)d_in[4];
    const float* ln_b = (const float*)d_in[5];
    const float* Wq   = (const float*)d_in[6];
    const float* bq   = (const float*)d_in[7];
    const float* Wk   = (const float*)d_in[8];
    const float* bk   = (const float*)d_in[9];
    const float* Wv   = (const float*)d_in[10];
    const float* bv   = (const float*)d_in[11];
    const float* Wo   = (const float*)d_in[12];
    const float* bo   = (const float*)d_in[13];
    const float* gw   = (const float*)d_in[14];
    const float* gb   = (const float*)d_in[15];
    const int* use_adj = (const int*)d_in[16];
    float* out = (float*)d_out;

    float *h, *q, *k, *v, *sc, *ctx, *h2;
    cudaGetSymbolAddress((void**)&h,   g_h);
    cudaGetSymbolAddress((void**)&q,   g_q);
    cudaGetSymbolAddress((void**)&k,   g_k);
    cudaGetSymbolAddress((void**)&v,   g_v);
    cudaGetSymbolAddress((void**)&sc,  g_sc);
    cudaGetSymbolAddress((void**)&ctx, g_ctx);
    cudaGetSymbolAddress((void**)&h2,  g_h2);
    __nv_bfloat16 *whi, *wlo;
    cudaGetSymbolAddress((void**)&whi, g_whi);
    cudaGetSymbolAddress((void**)&wlo, g_wlo);

    cudaFuncSetAttribute(gemm_mma, cudaFuncAttributeMaxDynamicSharedMemorySize, GM_TOTAL);

    // weight transpose + bf16 split (W_w=0, Wq=1, Wk=2, Wv=3, Wo=4)
    dim3 gPrep(16, 16, 5);
    prep_w<<<gPrep, dim3(32, 8)>>>(W_w, Wq, Wk, Wv, Wo);

    dim3 gGemm(4, 64);   // (N tiles, M tiles) for 128x128 CTA tiles
    const size_t WSZ = (size_t)DM * DM;

    // h = LN(x @ W_w + W_b)
    gemm_mma<<<gGemm, 256, GM_TOTAL>>>(x, whi + 0 * WSZ, wlo + 0 * WSZ, W_b, h, 0);
    ln_kernel<<<MR, 256>>>(h, ln_g, ln_b);

    // q, k, v projections
    gemm_mma<<<gGemm, 256, GM_TOTAL>>>(h, whi + 1 * WSZ, wlo + 1 * WSZ, bq, q, 0);
    gemm_mma<<<gGemm, 256, GM_TOTAL>>>(h, whi + 2 * WSZ, wlo + 2 * WSZ, bk, k, 0);
    gemm_mma<<<gGemm, 256, GM_TOTAL>>>(h, whi + 3 * WSZ, wlo + 3 * WSZ, bv, v, 0);

    // attention scores + mask
    dim3 gSc(SEQ / 64, SEQ / 64, NB * NH);  // (8, 8, 128)
    scores_kernel<<<gSc, 256>>>(q, k, adj, use_adj, sc);

    // softmax
    softmax_kernel<<<NB * NH * SEQ, 256>>>(sc);

    // ctx = attn @ V
    dim3 gCtx(SEQ / 64, NB * NH);           // (8, 128)
    ctx_kernel<<<gCtx, 256>>>(sc, v, ctx);

    // h2 = relu(ctx @ Wo + bo)
    gemm_mma<<<gGemm, 256, GM_TOTAL>>>(ctx, whi + 4 * WSZ, wlo + 4 * WSZ, bo, h2, 1);

    // gated residual
    gate_kernel<<<MR, 256>>>(x, h2, gw, gb, out);
}

// round 5
// speedup vs baseline: 2.0782x; 1.4195x over previous
#include <cuda_runtime.h>
#include <cuda_bf16.h>
#include <cstdint>

// Problem constants (fixed shapes)
constexpr int NB   = 16;          // batch
constexpr int SEQ  = 512;         // sequence length
constexpr int DM   = 512;         // model dim
constexpr int NH   = 8;           // heads
constexpr int DK   = 64;          // head dim
constexpr int MR   = NB * SEQ;    // 8192 rows
constexpr float SCALE = 0.125f;   // DK^-0.5
constexpr float NEGC  = -9000000000000000.0f;
constexpr float LN_EPS = 1e-5f;

// Scratch (device globals — no allocation allowed)
__device__ float g_h  [MR * DM];
__device__ float g_ctx[MR * DM];
__device__ float g_h2 [MR * DM];
// q/k/v as bf16 hi/lo split planes (written by projection GEMM epilogue)
__device__ __nv_bfloat16 g_qhi[MR * DM];
__device__ __nv_bfloat16 g_qlo[MR * DM];
__device__ __nv_bfloat16 g_khi[MR * DM];
__device__ __nv_bfloat16 g_klo[MR * DM];
__device__ __nv_bfloat16 g_vhi[MR * DM];
__device__ __nv_bfloat16 g_vlo[MR * DM];
// bf16 hi/lo split of the 5 transposed weights, layout [N, K]
__device__ __nv_bfloat16 g_whi[5 * DM * DM];
__device__ __nv_bfloat16 g_wlo[5 * DM * DM];

// ---------------------------------------------------------------------------
// Helpers
// ---------------------------------------------------------------------------
__device__ __forceinline__ uint32_t smem_u32(const void* p) {
    uint32_t a;
    asm("{ .reg .u64 t; cvta.to.shared.u64 t, %1; cvt.u32.u64 %0, t; }" : "=r"(a) : "l"(p));
    return a;
}
__device__ __forceinline__ uint32_t swz(uint32_t off) { return off ^ ((off >> 3) & 0x70); }

__device__ __forceinline__ void split_bf16(float a, __nv_bfloat16& hi, __nv_bfloat16& lo) {
    hi = __float2bfloat16(a);
    lo = __float2bfloat16(a - __bfloat162float(hi));
}
__device__ __forceinline__ uint32_t pack2(__nv_bfloat16 a, __nv_bfloat16 b) {
    return (uint32_t)__bfloat16_as_ushort(a) | ((uint32_t)__bfloat16_as_ushort(b) << 16);
}
__device__ __forceinline__ void pack_split2(float v0, float v1, uint32_t& hi, uint32_t& lo) {
    __nv_bfloat16 h0, h1, l0, l1;
    split_bf16(v0, h0, l0);
    split_bf16(v1, h1, l1);
    hi = pack2(h0, h1);
    lo = pack2(l0, l1);
}

__device__ __forceinline__ void ldsm_x4(uint32_t* r, uint32_t addr) {
    asm volatile("ldmatrix.sync.aligned.m8n8.x4.shared.b16 {%0,%1,%2,%3}, [%4];"
                 : "=r"(r[0]), "=r"(r[1]), "=r"(r[2]), "=r"(r[3]) : "r"(addr));
}
__device__ __forceinline__ void ldsm_x4_t(uint32_t* r, uint32_t addr) {
    asm volatile("ldmatrix.sync.aligned.m8n8.x4.trans.shared.b16 {%0,%1,%2,%3}, [%4];"
                 : "=r"(r[0]), "=r"(r[1]), "=r"(r[2]), "=r"(r[3]) : "r"(addr));
}
__device__ __forceinline__ void mma_bf16(float* d, const uint32_t* a, const uint32_t* b) {
    asm volatile(
        "mma.sync.aligned.m16n8k16.row.col.f32.bf16.bf16.f32 "
        "{%0,%1,%2,%3}, {%4,%5,%6,%7}, {%8,%9}, {%0,%1,%2,%3};"
        : "+f"(d[0]), "+f"(d[1]), "+f"(d[2]), "+f"(d[3])
        : "r"(a[0]), "r"(a[1]), "r"(a[2]), "r"(a[3]), "r"(b[0]), "r"(b[1]));
}

// ---------------------------------------------------------------------------
// Weight prep: transpose W[K=512, N=512] -> Whi/Wlo [N, K] bf16 split.
// grid = (16, 16, 5), block = (32, 8)
// ---------------------------------------------------------------------------
__global__ void __launch_bounds__(256) prep_w(
    const float* __restrict__ W0, const float* __restrict__ W1,
    const float* __restrict__ W2, const float* __restrict__ W3,
    const float* __restrict__ W4)
{
    const float* W;
    switch (blockIdx.z) {
        case 0: W = W0; break;
        case 1: W = W1; break;
        case 2: W = W2; break;
        case 3: W = W3; break;
        default: W = W4; break;
    }
    __nv_bfloat16* oh = g_whi + (size_t)blockIdx.z * DM * DM;
    __nv_bfloat16* ol = g_wlo + (size_t)blockIdx.z * DM * DM;

    __shared__ float s[32][33];
    const int bx = blockIdx.x * 32, by = blockIdx.y * 32;
    const int tx = threadIdx.x, ty = threadIdx.y;
#pragma unroll
    for (int i = 0; i < 4; i++)
        s[ty + i * 8][tx] = W[(size_t)(by + ty + i * 8) * DM + bx + tx];
    __syncthreads();
#pragma unroll
    for (int i = 0; i < 4; i++) {
        int n = bx + ty + i * 8;
        int k = by + tx;
        float v = s[tx][ty + i * 8];
        __nv_bfloat16 hi, lo;
        split_bf16(v, hi, lo);
        oh[(size_t)n * DM + k] = hi;
        ol[(size_t)n * DM + k] = lo;
    }
}

// ---------------------------------------------------------------------------
// mma.sync GEMM: C[MR x 512] = A[MR x 512] @ W + bias
// split==0: fp32 C output (optional relu).  split==1: bf16 hi/lo outputs.
// CTA: 128x128 tile, BK=64 staged, 8 warps (2M x 4N), warp tile 64x32.
// grid = (4, 64), 256 threads, 64KB dynamic smem.
// ---------------------------------------------------------------------------
constexpr int GM_AHI = 0;
constexpr int GM_ALO = 16384;
constexpr int GM_BHI = 32768;
constexpr int GM_BLO = 49152;
constexpr int GM_TOTAL = 65536;

__global__ void __launch_bounds__(256) gemm_mma(
    const float* __restrict__ A,
    const __nv_bfloat16* __restrict__ Bhi, const __nv_bfloat16* __restrict__ Blo,
    const float* __restrict__ bias, float* __restrict__ C,
    __nv_bfloat16* __restrict__ Chi, __nv_bfloat16* __restrict__ Clo,
    int relu, int split)
{
    extern __shared__ __align__(1024) char smem[];
    const uint32_t sb = smem_u32(smem);
    const int tid = threadIdx.x;
    const int lid = tid & 31;
    const int wid = tid >> 5;
    const int warpM = (wid >> 2) * 64;   // 0 or 64
    const int warpN = (wid & 3) * 32;    // 0,32,64,96
    const int rowBase = blockIdx.y * 128;
    const int colBase = blockIdx.x * 128;

    float acc[4][4][4];
#pragma unroll
    for (int i = 0; i < 4; i++)
#pragma unroll
        for (int j = 0; j < 4; j++)
#pragma unroll
            for (int r = 0; r < 4; r++) acc[i][j][r] = 0.f;

    const int a_row = (lid & 7) + ((lid >> 3) & 1) * 8;
    const int a_kh  = ((lid >> 4) & 1) * 8;
    const int b_nrow = (lid & 7) + ((lid >> 4) & 1) * 8;
    const int b_kh   = ((lid >> 3) & 1) * 8;

    for (int s = 0; s < 8; s++) {
        const int k0 = s * 64;
        // ---- A tile 128x64 fp32 -> hi/lo bf16 planes ----
#pragma unroll
        for (int it = 0; it < 8; it++) {
            int i = tid + it * 256;
            int row = i >> 4;
            int kk  = (i & 15) * 4;
            float4 v = *(const float4*)&A[(size_t)(rowBase + row) * DM + k0 + kk];
            __nv_bfloat16 h0, h1, h2, h3, l0, l1, l2, l3;
            split_bf16(v.x, h0, l0); split_bf16(v.y, h1, l1);
            split_bf16(v.z, h2, l2); split_bf16(v.w, h3, l3);
            uint32_t off = swz((uint32_t)(row * 128 + kk * 2));
            *(uint2*)(smem + GM_AHI + off) = make_uint2(pack2(h0, h1), pack2(h2, h3));
            *(uint2*)(smem + GM_ALO + off) = make_uint2(pack2(l0, l1), pack2(l2, l3));
        }
        // ---- B tile 128x64 bf16 (pre-split) ----
#pragma unroll
        for (int it = 0; it < 4; it++) {
            int i = tid + it * 256;
            int row = i >> 3;
            int kk  = (i & 7) * 8;
            size_t gidx = (size_t)(colBase + row) * DM + k0 + kk;
            uint32_t off = swz((uint32_t)(row * 128 + kk * 2));
            *(uint4*)(smem + GM_BHI + off) = *(const uint4*)&Bhi[gidx];
            *(uint4*)(smem + GM_BLO + off) = *(const uint4*)&Blo[gidx];
        }
        __syncthreads();

#pragma unroll
        for (int ks = 0; ks < 4; ks++) {
            uint32_t ahi[4][4], alo[4][4], bhi[8], blo[8];
#pragma unroll
            for (int mi = 0; mi < 4; mi++) {
                uint32_t off = swz((uint32_t)((warpM + mi * 16 + a_row) * 128 + (ks * 16 + a_kh) * 2));
                ldsm_x4(ahi[mi], sb + GM_AHI + off);
                ldsm_x4(alo[mi], sb + GM_ALO + off);
            }
#pragma unroll
            for (int np = 0; np < 2; np++) {
                uint32_t off = swz((uint32_t)((warpN + np * 16 + b_nrow) * 128 + (ks * 16 + b_kh) * 2));
                ldsm_x4(bhi + np * 4, sb + GM_BHI + off);
                ldsm_x4(blo + np * 4, sb + GM_BLO + off);
            }
#pragma unroll
            for (int mi = 0; mi < 4; mi++)
#pragma unroll
                for (int ni = 0; ni < 4; ni++) {
                    mma_bf16(acc[mi][ni], ahi[mi], bhi + ni * 2);
                    mma_bf16(acc[mi][ni], ahi[mi], blo + ni * 2);
                    mma_bf16(acc[mi][ni], alo[mi], bhi + ni * 2);
                }
        }
        __syncthreads();
    }

    // ---- epilogue ----
#pragma unroll
    for (int mi = 0; mi < 4; mi++) {
        int r0 = rowBase + warpM + mi * 16 + (lid >> 2);
#pragma unroll
        for (int ni = 0; ni < 4; ni++) {
            int c = colBase + warpN + ni * 8 + 2 * (lid & 3);
            float2 bb = *(const float2*)&bias[c];
            float v0 = acc[mi][ni][0] + bb.x;
            float v1 = acc[mi][ni][1] + bb.y;
            float v2 = acc[mi][ni][2] + bb.x;
            float v3 = acc[mi][ni][3] + bb.y;
            if (!split) {
                if (relu) {
                    v0 = fmaxf(v0, 0.f); v1 = fmaxf(v1, 0.f);
                    v2 = fmaxf(v2, 0.f); v3 = fmaxf(v3, 0.f);
                }
                *(float2*)&C[(size_t)r0 * DM + c]       = make_float2(v0, v1);
                *(float2*)&C[(size_t)(r0 + 8) * DM + c] = make_float2(v2, v3);
            } else {
                uint32_t h01, l01, h23, l23;
                pack_split2(v0, v1, h01, l01);
                pack_split2(v2, v3, h23, l23);
                *(uint32_t*)&Chi[(size_t)r0 * DM + c]       = h01;
                *(uint32_t*)&Clo[(size_t)r0 * DM + c]       = l01;
                *(uint32_t*)&Chi[(size_t)(r0 + 8) * DM + c] = h23;
                *(uint32_t*)&Clo[(size_t)(r0 + 8) * DM + c] = l23;
            }
        }
    }
}

// ---------------------------------------------------------------------------
// Fused attention: per CTA = one (b, h, 128-row q tile).
// S = Q@K^T (split bf16), exact mask, online softmax, O = P@V (split bf16).
// 8 warps; warp w owns rows w*16..w*16+15 of the q tile (full k extent).
// grid = (4, 128), 256 threads, 64KB smem.
// ---------------------------------------------------------------------------
constexpr int AT_QHI = 0;
constexpr int AT_QLO = 16384;
constexpr int AT_KHI = 32768;
constexpr int AT_KLO = 40960;
constexpr int AT_VHI = 49152;
constexpr int AT_VLO = 57344;
constexpr int AT_TOTAL = 65536;

__global__ void __launch_bounds__(256) attn_fused(
    const __nv_bfloat16* __restrict__ qhi, const __nv_bfloat16* __restrict__ qlo,
    const __nv_bfloat16* __restrict__ khi, const __nv_bfloat16* __restrict__ klo,
    const __nv_bfloat16* __restrict__ vhi, const __nv_bfloat16* __restrict__ vlo,
    const float* __restrict__ adj, const int* __restrict__ use_adj,
    float* __restrict__ ctx)
{
    extern __shared__ __align__(1024) char smem[];
    const uint32_t sb = smem_u32(smem);
    const int tid = threadIdx.x, lid = tid & 31, wid = tid >> 5;
    const int qt = blockIdx.x;
    const int bh = blockIdx.y;
    const int b  = bh >> 3, h = bh & 7;
    const int ua = *use_adj;

    const size_t rowbase = (size_t)(b * SEQ + qt * 128);

    // ---- stage Q tile (128 x 64, hi/lo planes) ----
    for (int i = tid; i < 1024; i += 256) {
        int r = i >> 3, seg = i & 7;
        size_t g = (rowbase + r) * DM + h * 64 + seg * 8;
        uint32_t off = swz((uint32_t)(r * 128 + seg * 16));
        *(uint4*)(smem + AT_QHI + off) = *(const uint4*)&qhi[g];
        *(uint4*)(smem + AT_QLO + off) = *(const uint4*)&qlo[g];
    }
    __syncthreads();

    const int a_row  = (lid & 7) + ((lid >> 3) & 1) * 8;
    const int a_kh   = ((lid >> 4) & 1) * 8;
    const int b_nrow = (lid & 7) + ((lid >> 4) & 1) * 8;
    const int b_kh   = ((lid >> 3) & 1) * 8;

    uint32_t qaH[4][4], qaL[4][4];
#pragma unroll
    for (int ks = 0; ks < 4; ks++) {
        uint32_t off = swz((uint32_t)((wid * 16 + a_row) * 128 + (ks * 16 + a_kh) * 2));
        ldsm_x4(qaH[ks], sb + AT_QHI + off);
        ldsm_x4(qaL[ks], sb + AT_QLO + off);
    }

    float oacc[8][4];
#pragma unroll
    for (int i = 0; i < 8; i++)
#pragma unroll
        for (int j = 0; j < 4; j++) oacc[i][j] = 0.f;
    float m0 = -3.0e38f, m1 = -3.0e38f, l0 = 0.f, l1 = 0.f;
    const int ra = lid >> 2;         // row within warp tile (rb = ra + 8)
    const int cq = (lid & 3) * 2;    // col pair base within n-tile

    for (int kt = 0; kt < 8; kt++) {
        // ---- stage K/V tiles (64 x 64 each, hi/lo planes) ----
        for (int i = tid; i < 512; i += 256) {
            int r = i >> 3, seg = i & 7;
            size_t g = ((size_t)(b * SEQ + kt * 64 + r)) * DM + h * 64 + seg * 8;
            uint32_t off = swz((uint32_t)(r * 128 + seg * 16));
            *(uint4*)(smem + AT_KHI + off) = *(const uint4*)&khi[g];
            *(uint4*)(smem + AT_KLO + off) = *(const uint4*)&klo[g];
            *(uint4*)(smem + AT_VHI + off) = *(const uint4*)&vhi[g];
            *(uint4*)(smem + AT_VLO + off) = *(const uint4*)&vlo[g];
        }
        __syncthreads();

        // ---- S = Q @ K^T  (warp: 16 x 64) ----
        float sacc[8][4];
#pragma unroll
        for (int i = 0; i < 8; i++)
#pragma unroll
            for (int j = 0; j < 4; j++) sacc[i][j] = 0.f;
#pragma unroll
        for (int ks = 0; ks < 4; ks++) {
            uint32_t kbH[4][4], kbL[4][4];
#pragma unroll
            for (int p = 0; p < 4; p++) {
                uint32_t off = swz((uint32_t)((p * 16 + b_nrow) * 128 + (ks * 16 + b_kh) * 2));
                ldsm_x4(kbH[p], sb + AT_KHI + off);
                ldsm_x4(kbL[p], sb + AT_KLO + off);
            }
#pragma unroll
            for (int nt = 0; nt < 8; nt++) {
                const uint32_t* bh_ = &kbH[nt >> 1][(nt & 1) * 2];
                const uint32_t* bl_ = &kbL[nt >> 1][(nt & 1) * 2];
                mma_bf16(sacc[nt], qaH[ks], bh_);
                mma_bf16(sacc[nt], qaH[ks], bl_);
                mma_bf16(sacc[nt], qaL[ks], bh_);
            }
        }

        // ---- scale + exact mask ----
        const float* adjq = adj + ((size_t)b * SEQ + qt * 128 + wid * 16) * SEQ + kt * 64;
#pragma unroll
        for (int nt = 0; nt < 8; nt++) {
            float v0 = sacc[nt][0] * SCALE, v1 = sacc[nt][1] * SCALE;
            float v2 = sacc[nt][2] * SCALE, v3 = sacc[nt][3] * SCALE;
            if (ua) {
                int c = nt * 8 + cq;
                float2 aa = *(const float2*)&adjq[(size_t)ra * SEQ + c];
                float2 ab = *(const float2*)&adjq[(size_t)(ra + 8) * SEQ + c];
                v0 = (aa.x > 0.f ? v0 : NEGC) * aa.x;
                v1 = (aa.y > 0.f ? v1 : NEGC) * aa.y;
                v2 = (ab.x > 0.f ? v2 : NEGC) * ab.x;
                v3 = (ab.y > 0.f ? v3 : NEGC) * ab.y;
            }
            sacc[nt][0] = v0; sacc[nt][1] = v1; sacc[nt][2] = v2; sacc[nt][3] = v3;
        }

        // ---- online softmax ----
        float mx0 = -3.0e38f, mx1 = -3.0e38f;
#pragma unroll
        for (int nt = 0; nt < 8; nt++) {
            mx0 = fmaxf(mx0, fmaxf(sacc[nt][0], sacc[nt][1]));
            mx1 = fmaxf(mx1, fmaxf(sacc[nt][2], sacc[nt][3]));
        }
        mx0 = fmaxf(mx0, __shfl_xor_sync(0xffffffffu, mx0, 1));
        mx0 = fmaxf(mx0, __shfl_xor_sync(0xffffffffu, mx0, 2));
        mx1 = fmaxf(mx1, __shfl_xor_sync(0xffffffffu, mx1, 1));
        mx1 = fmaxf(mx1, __shfl_xor_sync(0xffffffffu, mx1, 2));
        float mn0 = fmaxf(m0, mx0), mn1 = fmaxf(m1, mx1);
        float al0 = __expf(m0 - mn0), al1 = __expf(m1 - mn1);
        m0 = mn0; m1 = mn1;
        l0 *= al0; l1 *= al1;
#pragma unroll
        for (int nt = 0; nt < 8; nt++) {
            oacc[nt][0] *= al0; oacc[nt][1] *= al0;
            oacc[nt][2] *= al1; oacc[nt][3] *= al1;
        }
#pragma unroll
        for (int nt = 0; nt < 8; nt++) {
            float p0 = __expf(sacc[nt][0] - m0);
            float p1 = __expf(sacc[nt][1] - m0);
            float p2 = __expf(sacc[nt][2] - m1);
            float p3 = __expf(sacc[nt][3] - m1);
            l0 += p0 + p1; l1 += p2 + p3;
            sacc[nt][0] = p0; sacc[nt][1] = p1; sacc[nt][2] = p2; sacc[nt][3] = p3;
        }

        // ---- O += P @ V  (P A-frags straight from S accumulators) ----
#pragma unroll
        for (int k2 = 0; k2 < 4; k2++) {
            uint32_t paH[4], paL[4];
            pack_split2(sacc[2 * k2][0],     sacc[2 * k2][1],     paH[0], paL[0]);
            pack_split2(sacc[2 * k2][2],     sacc[2 * k2][3],     paH[1], paL[1]);
            pack_split2(sacc[2 * k2 + 1][0], sacc[2 * k2 + 1][1], paH[2], paL[2]);
            pack_split2(sacc[2 * k2 + 1][2], sacc[2 * k2 + 1][3], paH[3], paL[3]);
            uint32_t vbH[4][4], vbL[4][4];
#pragma unroll
            for (int p = 0; p < 4; p++) {
                uint32_t off = swz((uint32_t)((k2 * 16 + (lid & 7) + ((lid >> 3) & 1) * 8) * 128
                                              + (p * 16 + (lid >> 4) * 8) * 2));
                ldsm_x4_t(vbH[p], sb + AT_VHI + off);
                ldsm_x4_t(vbL[p], sb + AT_VLO + off);
            }
#pragma unroll
            for (int nt = 0; nt < 8; nt++) {
                const uint32_t* bh_ = &vbH[nt >> 1][(nt & 1) * 2];
                const uint32_t* bl_ = &vbL[nt >> 1][(nt & 1) * 2];
                mma_bf16(oacc[nt], paH, bh_);
                mma_bf16(oacc[nt], paH, bl_);
                mma_bf16(oacc[nt], paL, bh_);
            }
        }
        __syncthreads();
    }

    // ---- finalize: reduce l across quad, normalize, store ctx fp32 ----
    l0 += __shfl_xor_sync(0xffffffffu, l0, 1);
    l0 += __shfl_xor_sync(0xffffffffu, l0, 2);
    l1 += __shfl_xor_sync(0xffffffffu, l1, 1);
    l1 += __shfl_xor_sync(0xffffffffu, l1, 2);
    float inv0 = 1.f / l0, inv1 = 1.f / l1;
    size_t r0g = rowbase + wid * 16 + ra;
#pragma unroll
    for (int nt = 0; nt < 8; nt++) {
        int c = h * 64 + nt * 8 + cq;
        *(float2*)&ctx[r0g * DM + c]       = make_float2(oacc[nt][0] * inv0, oacc[nt][1] * inv0);
        *(float2*)&ctx[(r0g + 8) * DM + c] = make_float2(oacc[nt][2] * inv1, oacc[nt][3] * inv1);
    }
}

// ---------------------------------------------------------------------------
// Reductions
// ---------------------------------------------------------------------------
__device__ __forceinline__ float warpReduceSum(float v) {
#pragma unroll
    for (int o = 16; o; o >>= 1) v += __shfl_xor_sync(0xffffffffu, v, o);
    return v;
}
__device__ __forceinline__ float blockReduceSum(float v) {
    __shared__ float sh[8];
    v = warpReduceSum(v);
    if ((threadIdx.x & 31) == 0) sh[threadIdx.x >> 5] = v;
    __syncthreads();
    float r = (threadIdx.x < 8) ? sh[threadIdx.x] : 0.f;
    if (threadIdx.x < 32) r = warpReduceSum(r);
    if (threadIdx.x == 0) sh[0] = r;
    __syncthreads();
    float out = sh[0];
    __syncthreads();
    return out;
}

// ---------------------------------------------------------------------------
// LayerNorm over last dim (512), in-place. grid = MR, 256 threads.
// ---------------------------------------------------------------------------
__global__ void __launch_bounds__(256) ln_kernel(
    float* __restrict__ h, const float* __restrict__ g, const float* __restrict__ b)
{
    const int row = blockIdx.x;
    float* p = h + (size_t)row * DM;
    const int t = threadIdx.x;
    float v0 = p[t], v1 = p[t + 256];
    float mu = blockReduceSum(v0 + v1) * (1.f / DM);
    float d0 = v0 - mu, d1 = v1 - mu;
    float var = blockReduceSum(d0 * d0 + d1 * d1) * (1.f / DM);
    float rs = rsqrtf(var + LN_EPS);
    p[t]       = d0 * rs * g[t]       + b[t];
    p[t + 256] = d1 * rs * g[t + 256] + b[t + 256];
}

// ---------------------------------------------------------------------------
// Gate: coeff = sigmoid([x, h2] @ gw + gb); out = coeff*x + (1-coeff)*h2
// grid = MR, 256 threads.
// ---------------------------------------------------------------------------
__global__ void __launch_bounds__(256) gate_kernel(
    const float* __restrict__ x, const float* __restrict__ h2,
    const float* __restrict__ gw, const float* __restrict__ gb,
    float* __restrict__ out)
{
    const int row = blockIdx.x;
    const float* xr = x  + (size_t)row * DM;
    const float* hr = h2 + (size_t)row * DM;
    const int t = threadIdx.x;
    float s = xr[t] * gw[t] + xr[t + 256] * gw[t + 256]
            + hr[t] * gw[DM + t] + hr[t + 256] * gw[DM + t + 256];
    s = blockReduceSum(s) + gb[0];
    float c = 1.f / (1.f + __expf(-s));
    float* o = out + (size_t)row * DM;
    o[t]       = c * xr[t]       + (1.f - c) * hr[t];
    o[t + 256] = c * xr[t + 256] + (1.f - c) * hr[t + 256];
}

// ---------------------------------------------------------------------------
// Launch
// ---------------------------------------------------------------------------
extern "C" void kernel_launch(void* const* d_in, const int* in_sizes, int n_in,
                              void* d_out, int out_size)
{
    const float* x    = (const float*)d_in[0];
    const float* adj  = (const float*)d_in[1];
    const float* W_w  = (const float*)d_in[2];
    const float* W_b  = (const float*)d_in[3];
    const float* ln_g = (const float*)d_in[4];
    const float* ln_b = (const float*)d_in[5];
    const float* Wq   = (const float*)d_in[6];
    const float* bq   = (const float*)d_in[7];
    const float* Wk   = (const float*)d_in[8];
    const float* bk   = (const float*)d_in[9];
    const float* Wv   = (const float*)d_in[10];
    const float* bv   = (const float*)d_in[11];
    const float* Wo   = (const float*)d_in[12];
    const float* bo   = (const float*)d_in[13];
    const float* gw   = (const float*)d_in[14];
    const float* gb   = (const float*)d_in[15];
    const int* use_adj = (const int*)d_in[16];
    float* out = (float*)d_out;

    float *h, *ctx, *h2;
    cudaGetSymbolAddress((void**)&h,   g_h);
    cudaGetSymbolAddress((void**)&ctx, g_ctx);
    cudaGetSymbolAddress((void**)&h2,  g_h2);
    __nv_bfloat16 *whi, *wlo, *qhi, *qlo, *khi, *klo, *vhi, *vlo;
    cudaGetSymbolAddress((void**)&whi, g_whi);
    cudaGetSymbolAddress((void**)&wlo, g_wlo);
    cudaGetSymbolAddress((void**)&qhi, g_qhi);
    cudaGetSymbolAddress((void**)&qlo, g_qlo);
    cudaGetSymbolAddress((void**)&khi, g_khi);
    cudaGetSymbolAddress((void**)&klo, g_klo);
    cudaGetSymbolAddress((void**)&vhi, g_vhi);
    cudaGetSymbolAddress((void**)&vlo, g_vlo);

    cudaFuncSetAttribute(gemm_mma,   cudaFuncAttributeMaxDynamicSharedMemorySize, GM_TOTAL);
    cudaFuncSetAttribute(attn_fused, cudaFuncAttributeMaxDynamicSharedMemorySize, AT_TOTAL);

    // weight transpose + bf16 split (W_w=0, Wq=1, Wk=2, Wv=3, Wo=4)
    dim3 gPrep(16, 16, 5);
    prep_w<<<gPrep, dim3(32, 8)>>>(W_w, Wq, Wk, Wv, Wo);

    dim3 gGemm(4, 64);
    const size_t WSZ = (size_t)DM * DM;

    // h = LN(x @ W_w + W_b)
    gemm_mma<<<gGemm, 256, GM_TOTAL>>>(x, whi + 0 * WSZ, wlo + 0 * WSZ, W_b, h,
                                       nullptr, nullptr, 0, 0);
    ln_kernel<<<MR, 256>>>(h, ln_g, ln_b);

    // q, k, v projections (split bf16 outputs)
    gemm_mma<<<gGemm, 256, GM_TOTAL>>>(h, whi + 1 * WSZ, wlo + 1 * WSZ, bq, nullptr,
                                       qhi, qlo, 0, 1);
    gemm_mma<<<gGemm, 256, GM_TOTAL>>>(h, whi + 2 * WSZ, wlo + 2 * WSZ, bk, nullptr,
                                       khi, klo, 0, 1);
    gemm_mma<<<gGemm, 256, GM_TOTAL>>>(h, whi + 3 * WSZ, wlo + 3 * WSZ, bv, nullptr,
                                       vhi, vlo, 0, 1);

    // fused attention -> ctx (fp32)
    dim3 gAttn(SEQ / 128, NB * NH);   // (4, 128)
    attn_fused<<<gAttn, 256, AT_TOTAL>>>(qhi, qlo, khi, klo, vhi, vlo, adj, use_adj, ctx);

    // h2 = relu(ctx @ Wo + bo)
    gemm_mma<<<gGemm, 256, GM_TOTAL>>>(ctx, whi + 4 * WSZ, wlo + 4 * WSZ, bo, h2,
                                       nullptr, nullptr, 1, 0);

    // gated residual
    gate_kernel<<<MR, 256>>>(x, h2, gw, gb, out);
}